// round 3
// baseline (speedup 1.0000x reference)
#include <cuda_runtime.h>
#include <math.h>

// Problem constants
#define BB 8
#define LL 1024
#define DD 512
#define HH 8
#define DH 64
#define INNER 512
#define ROWS (BB*LL)          // 8192
#define EPSV 1e-5f

// ---------------- scratch (device globals; no allocation) ----------------
__device__ float g_xn [ROWS*DD];          // 16 MB  LayerNorm output
__device__ float g_pe [LL*DD];            //  2 MB  rel-pos embedding table
__device__ float g_pos[HH*LL*DH];         //  2 MB  (H,L,Dh)
__device__ float g_q  [BB*HH*LL*DH];      // 16 MB  (B,H,L,Dh)
__device__ float g_k  [BB*HH*LL*DH];
__device__ float g_v  [BB*HH*LL*DH];
__device__ float g_att[ROWS*INNER];       // 16 MB  (B,L,H*Dh)

// ---------------- LayerNorm: one block per row ----------------
__global__ void ln_kernel(const float* __restrict__ x,
                          const float* __restrict__ gamma,
                          const float* __restrict__ beta,
                          float* __restrict__ xn) {
    int row = blockIdx.x;
    const float* xr = x + (size_t)row * DD;
    int t = threadIdx.x;                       // 256 threads
    float a = xr[t], b = xr[t + 256];
    float s = a + b, sq = a*a + b*b;
    #pragma unroll
    for (int o = 16; o; o >>= 1) {
        s  += __shfl_xor_sync(0xffffffffu, s,  o);
        sq += __shfl_xor_sync(0xffffffffu, sq, o);
    }
    __shared__ float ss[8], ssq[8];
    if ((t & 31) == 0) { ss[t >> 5] = s; ssq[t >> 5] = sq; }
    __syncthreads();
    float ts = 0.f, tsq = 0.f;
    #pragma unroll
    for (int i = 0; i < 8; i++) { ts += ss[i]; tsq += ssq[i]; }
    float mu  = ts * (1.f / DD);
    float var = fmaxf(tsq * (1.f / DD) - mu * mu, 0.f);
    float rs  = rsqrtf(var + EPSV);
    float* o = xn + (size_t)row * DD;
    o[t]       = (a - mu) * rs * gamma[t]       + beta[t];
    o[t + 256] = (b - mu) * rs * gamma[t + 256] + beta[t + 256];
}

// ---------------- PE table ----------------
__global__ void pe_kernel(float* __restrict__ pe) {
    int idx = blockIdx.x * blockDim.x + threadIdx.x;   // LL*DD elems
    if (idx >= LL * DD) return;
    int i = idx >> 9;          // seq pos
    int j = idx & 511;         // feature
    double freq  = exp(-2.0 * (double)j * log(10000.0) / 512.0);
    double angle = (double)(i - j) * freq;
    pe[idx] = ((j & 1) == 0) ? (float)cos(angle) : (float)sin(angle);
}

// ---------------- tiled GEMM: C[M,N] = A[M,K] * Bt[N,K]^T (+bias) ----------------
// MODE 0: plain row-major C     (out projection -> d_out)
// MODE 1: scatter to g_q/g_k/g_v (QKV)
// MODE 2: scatter to g_pos       (position embedding projection)
template<int MODE>
__global__ void gemm64(const float* __restrict__ A, const float* __restrict__ Bt,
                       const float* __restrict__ bias, float* __restrict__ C,
                       int M, int N, int K) {
    __shared__ float As[64][17];
    __shared__ float Bs[64][17];
    int bm = blockIdx.y * 64, bn = blockIdx.x * 64;
    int tid = threadIdx.x;                // 256
    int tx = tid & 15, ty = tid >> 4;     // 16x16 threads, 4x4 each
    int lr = tid >> 2, lc4 = (tid & 3) << 2;
    float acc[4][4];
    #pragma unroll
    for (int i = 0; i < 4; i++)
        #pragma unroll
        for (int j = 0; j < 4; j++) acc[i][j] = 0.f;

    for (int k0 = 0; k0 < K; k0 += 16) {
        float4 a4 = *(const float4*)(A  + (size_t)(bm + lr) * K + k0 + lc4);
        float4 b4 = *(const float4*)(Bt + (size_t)(bn + lr) * K + k0 + lc4);
        As[lr][lc4] = a4.x; As[lr][lc4+1] = a4.y; As[lr][lc4+2] = a4.z; As[lr][lc4+3] = a4.w;
        Bs[lr][lc4] = b4.x; Bs[lr][lc4+1] = b4.y; Bs[lr][lc4+2] = b4.z; Bs[lr][lc4+3] = b4.w;
        __syncthreads();
        #pragma unroll
        for (int kk = 0; kk < 16; kk++) {
            float ar[4], br[4];
            #pragma unroll
            for (int i = 0; i < 4; i++) ar[i] = As[ty*4 + i][kk];
            #pragma unroll
            for (int j = 0; j < 4; j++) br[j] = Bs[tx*4 + j][kk];
            #pragma unroll
            for (int i = 0; i < 4; i++)
                #pragma unroll
                for (int j = 0; j < 4; j++) acc[i][j] += ar[i] * br[j];
        }
        __syncthreads();
    }
    #pragma unroll
    for (int i = 0; i < 4; i++) {
        int r = bm + ty*4 + i;
        #pragma unroll
        for (int j = 0; j < 4; j++) {
            int c = bn + tx*4 + j;
            float val = acc[i][j] + (bias ? bias[c] : 0.f);
            if (MODE == 0) {
                C[(size_t)r * N + c] = val;
            } else if (MODE == 1) {
                int which = c >> 9, rem = c & 511;
                int h = rem >> 6, dh = rem & 63;
                int b = r >> 10, l = r & 1023;
                float* dst = (which == 0) ? g_q : (which == 1) ? g_k : g_v;
                dst[(((size_t)b * HH + h) * LL + l) * DH + dh] = val;
            } else { // MODE 2
                int h = c >> 6, dh = c & 63;
                g_pos[((size_t)h * LL + r) * DH + dh] = val;
            }
        }
    }
}

// ---------------- flash-style attention ----------------
// grid: (L/64, B*H), block 256 threads, dynamic smem
// scores(l,m) = (q+u)·k_m + (q+v_bias)·pos_m, scaled by 1/8, online softmax, AV.
#define LDK 65
__global__ void attn_kernel(const float* __restrict__ u_bias,
                            const float* __restrict__ v_bias) {
    extern __shared__ float sm[];
    float* squ = sm;                    // 64 x LDK
    float* sqv = squ + 64*LDK;          // 64 x LDK
    float* sk  = sqv + 64*LDK;          // 64 x LDK
    float* sp  = sk  + 64*LDK;          // 64 x LDK
    float* sv  = sp  + 64*LDK;          // 64 x 64 (float4-friendly)
    float* ssc = sv  + 64*64;           // 64 x LDK

    int bh = blockIdx.y;
    int b = bh >> 3, h = bh & 7;
    int q0 = blockIdx.x * 64;
    int tid = threadIdx.x;

    const float* qbase = g_q   + (size_t)bh * LL * DH;
    const float* kbase = g_k   + (size_t)bh * LL * DH;
    const float* vbase = g_v   + (size_t)bh * LL * DH;
    const float* pbase = g_pos + (size_t)h  * LL * DH;

    // load q tile + biases
    for (int e4 = tid; e4 < 1024; e4 += 256) {
        int r = e4 >> 4, c4 = (e4 & 15) << 2;
        float4 q4 = *(const float4*)(qbase + (size_t)(q0 + r) * DH + c4);
        const float* up = u_bias + h*DH + c4;
        const float* vp = v_bias + h*DH + c4;
        squ[r*LDK + c4]   = q4.x + up[0];
        squ[r*LDK + c4+1] = q4.y + up[1];
        squ[r*LDK + c4+2] = q4.z + up[2];
        squ[r*LDK + c4+3] = q4.w + up[3];
        sqv[r*LDK + c4]   = q4.x + vp[0];
        sqv[r*LDK + c4+1] = q4.y + vp[1];
        sqv[r*LDK + c4+2] = q4.z + vp[2];
        sqv[r*LDK + c4+3] = q4.w + vp[3];
    }

    int row = tid >> 2, tc = tid & 3;   // phase-B mapping: 4 threads/row
    int tyy = tid >> 4, txx = tid & 15; // phase-A mapping: 16x16
    float mi = -INFINITY, li = 0.f;
    float acc[16];
    #pragma unroll
    for (int ii = 0; ii < 16; ii++) acc[ii] = 0.f;

    for (int kt = 0; kt < LL / 64; kt++) {
        __syncthreads();   // previous iter's phase-B readers done; also orders q-tile writes before first use
        // load K / pos / V tiles
        for (int e4 = tid; e4 < 1024; e4 += 256) {
            int m = e4 >> 4, c4 = (e4 & 15) << 2;
            size_t goff = (size_t)(kt*64 + m) * DH + c4;
            float4 k4 = *(const float4*)(kbase + goff);
            float4 p4 = *(const float4*)(pbase + goff);
            float4 v4 = *(const float4*)(vbase + goff);
            sk[m*LDK + c4] = k4.x; sk[m*LDK + c4+1] = k4.y; sk[m*LDK + c4+2] = k4.z; sk[m*LDK + c4+3] = k4.w;
            sp[m*LDK + c4] = p4.x; sp[m*LDK + c4+1] = p4.y; sp[m*LDK + c4+2] = p4.z; sp[m*LDK + c4+3] = p4.w;
            *(float4*)(sv + m*64 + c4) = v4;
        }
        __syncthreads();

        // phase A: 64x64 scores, 4x4 register blocking per thread
        {
            int r0 = tyy * 4, m0 = txx * 4;
            float s[4][4];
            #pragma unroll
            for (int i = 0; i < 4; i++)
                #pragma unroll
                for (int j = 0; j < 4; j++) s[i][j] = 0.f;
            #pragma unroll 8
            for (int d = 0; d < 64; d++) {
                float a0 = squ[(r0+0)*LDK + d], a1 = squ[(r0+1)*LDK + d];
                float a2 = squ[(r0+2)*LDK + d], a3 = squ[(r0+3)*LDK + d];
                float k0v = sk[(m0+0)*LDK + d], k1v = sk[(m0+1)*LDK + d];
                float k2v = sk[(m0+2)*LDK + d], k3v = sk[(m0+3)*LDK + d];
                s[0][0] += a0*k0v; s[0][1] += a0*k1v; s[0][2] += a0*k2v; s[0][3] += a0*k3v;
                s[1][0] += a1*k0v; s[1][1] += a1*k1v; s[1][2] += a1*k2v; s[1][3] += a1*k3v;
                s[2][0] += a2*k0v; s[2][1] += a2*k1v; s[2][2] += a2*k2v; s[2][3] += a2*k3v;
                s[3][0] += a3*k0v; s[3][1] += a3*k1v; s[3][2] += a3*k2v; s[3][3] += a3*k3v;
                float b0 = sqv[(r0+0)*LDK + d], b1 = sqv[(r0+1)*LDK + d];
                float b2 = sqv[(r0+2)*LDK + d], b3 = sqv[(r0+3)*LDK + d];
                float p0 = sp[(m0+0)*LDK + d], p1 = sp[(m0+1)*LDK + d];
                float p2 = sp[(m0+2)*LDK + d], p3 = sp[(m0+3)*LDK + d];
                s[0][0] += b0*p0; s[0][1] += b0*p1; s[0][2] += b0*p2; s[0][3] += b0*p3;
                s[1][0] += b1*p0; s[1][1] += b1*p1; s[1][2] += b1*p2; s[1][3] += b1*p3;
                s[2][0] += b2*p0; s[2][1] += b2*p1; s[2][2] += b2*p2; s[2][3] += b2*p3;
                s[3][0] += b3*p0; s[3][1] += b3*p1; s[3][2] += b3*p2; s[3][3] += b3*p3;
            }
            #pragma unroll
            for (int i = 0; i < 4; i++)
                #pragma unroll
                for (int j = 0; j < 4; j++)
                    ssc[(r0+i)*LDK + m0 + j] = s[i][j] * 0.125f;
        }
        __syncthreads();

        // phase B: online softmax + AV (4 threads per row, 16 out dims each)
        {
            float tmax = mi;
            #pragma unroll 16
            for (int m = 0; m < 64; m++) tmax = fmaxf(tmax, ssc[row*LDK + m]);
            float alpha = expf(mi - tmax);
            mi = tmax;
            li *= alpha;
            #pragma unroll
            for (int ii = 0; ii < 16; ii++) acc[ii] *= alpha;
            for (int m = 0; m < 64; m++) {
                float p = expf(ssc[row*LDK + m] - tmax);
                li += p;
                const float4* vp4 = (const float4*)(sv + m*64 + tc*16);
                float4 va = vp4[0], vb = vp4[1], vc = vp4[2], vd = vp4[3];
                acc[0]  += p*va.x; acc[1]  += p*va.y; acc[2]  += p*va.z; acc[3]  += p*va.w;
                acc[4]  += p*vb.x; acc[5]  += p*vb.y; acc[6]  += p*vb.z; acc[7]  += p*vb.w;
                acc[8]  += p*vc.x; acc[9]  += p*vc.y; acc[10] += p*vc.z; acc[11] += p*vc.w;
                acc[12] += p*vd.x; acc[13] += p*vd.y; acc[14] += p*vd.z; acc[15] += p*vd.w;
            }
        }
    }

    // epilogue: write (B, L, H*Dh)
    float inv = 1.f / li;
    float* out = g_att + ((size_t)(b * LL + q0 + row)) * INNER + h * DH + tc * 16;
    #pragma unroll
    for (int ii = 0; ii < 16; ii++) out[ii] = acc[ii] * inv;
}

// ---------------- launch ----------------
extern "C" void kernel_launch(void* const* d_in, const int* in_sizes, int n_in,
                              void* d_out, int out_size) {
    const float* x      = (const float*)d_in[0];
    const float* gamma  = (const float*)d_in[1];
    const float* beta   = (const float*)d_in[2];
    const float* w_qkv  = (const float*)d_in[3];
    const float* b_qkv  = (const float*)d_in[4];
    const float* w_pos  = (const float*)d_in[5];
    const float* w_out  = (const float*)d_in[6];
    const float* b_out  = (const float*)d_in[7];
    const float* u_bias = (const float*)d_in[8];
    const float* v_bias = (const float*)d_in[9];
    float* out = (float*)d_out;

    float *p_xn, *p_pe, *p_att;
    cudaGetSymbolAddress((void**)&p_xn,  g_xn);
    cudaGetSymbolAddress((void**)&p_pe,  g_pe);
    cudaGetSymbolAddress((void**)&p_att, g_att);

    // 1. LayerNorm
    ln_kernel<<<ROWS, 256>>>(x, gamma, beta, p_xn);

    // 2. PE table
    pe_kernel<<<(LL*DD + 255) / 256, 256>>>(p_pe);

    // 3. pos = PE @ w_pos^T  -> g_pos (scatter)
    {
        dim3 grid(INNER / 64, LL / 64);
        gemm64<2><<<grid, 256>>>(p_pe, w_pos, nullptr, nullptr, LL, INNER, DD);
    }

    // 4. QKV GEMM -> g_q/g_k/g_v (scatter)
    {
        dim3 grid((3 * INNER) / 64, ROWS / 64);
        gemm64<1><<<grid, 256>>>(p_xn, w_qkv, b_qkv, nullptr, ROWS, 3 * INNER, DD);
    }

    // 5. attention
    {
        int smem = (64*LDK*5 + 64*64) * (int)sizeof(float);  // 99584 B
        cudaFuncSetAttribute(attn_kernel, cudaFuncAttributeMaxDynamicSharedMemorySize, smem);
        dim3 grid(LL / 64, BB * HH);
        attn_kernel<<<grid, 256, smem>>>(u_bias, v_bias);
    }

    // 6. out projection -> d_out
    {
        dim3 grid(DD / 64, ROWS / 64);
        gemm64<0><<<grid, 256>>>(p_att, w_out, b_out, out, ROWS, DD, INNER);
    }
}

// round 4
// speedup vs baseline: 3.1041x; 3.1041x over previous
#include <cuda_runtime.h>
#include <math.h>

// Problem constants
#define BB 8
#define LL 1024
#define DD 512
#define HH 8
#define DH 64
#define INNER 512
#define ROWS (BB*LL)          // 8192
#define EPSV 1e-5f

// ---------------- scratch (device globals; no allocation) ----------------
__device__ float g_xn [ROWS*DD];
__device__ float g_pe [LL*DD];
__device__ float g_pos[HH*LL*DH];
__device__ float g_q  [BB*HH*LL*DH];
__device__ float g_k  [BB*HH*LL*DH];
__device__ float g_v  [BB*HH*LL*DH];
__device__ float g_att[ROWS*INNER];

// ---------------- tf32 helpers ----------------
__device__ __forceinline__ unsigned f2tf(float x) {
    unsigned r; asm("cvt.rna.tf32.f32 %0, %1;" : "=r"(r) : "f"(x)); return r;
}
__device__ __forceinline__ float f2tff(float x) { return __uint_as_float(f2tf(x)); }

__device__ __forceinline__ void mma_tf32(float c[4], const unsigned a[4], const unsigned b[2]) {
    asm volatile(
        "mma.sync.aligned.m16n8k8.row.col.f32.tf32.tf32.f32 "
        "{%0,%1,%2,%3}, {%4,%5,%6,%7}, {%8,%9}, {%0,%1,%2,%3};"
        : "+f"(c[0]), "+f"(c[1]), "+f"(c[2]), "+f"(c[3])
        : "r"(a[0]), "r"(a[1]), "r"(a[2]), "r"(a[3]), "r"(b[0]), "r"(b[1]));
}

// ---------------- LayerNorm: one block per row ----------------
__global__ void ln_kernel(const float* __restrict__ x,
                          const float* __restrict__ gamma,
                          const float* __restrict__ beta,
                          float* __restrict__ xn) {
    int row = blockIdx.x;
    const float* xr = x + (size_t)row * DD;
    int t = threadIdx.x;                       // 256 threads
    float a = xr[t], b = xr[t + 256];
    float s = a + b, sq = a*a + b*b;
    #pragma unroll
    for (int o = 16; o; o >>= 1) {
        s  += __shfl_xor_sync(0xffffffffu, s,  o);
        sq += __shfl_xor_sync(0xffffffffu, sq, o);
    }
    __shared__ float ss[8], ssq[8];
    if ((t & 31) == 0) { ss[t >> 5] = s; ssq[t >> 5] = sq; }
    __syncthreads();
    float ts = 0.f, tsq = 0.f;
    #pragma unroll
    for (int i = 0; i < 8; i++) { ts += ss[i]; tsq += ssq[i]; }
    float mu  = ts * (1.f / DD);
    float var = fmaxf(tsq * (1.f / DD) - mu * mu, 0.f);
    float rs  = rsqrtf(var + EPSV);
    float* o = xn + (size_t)row * DD;
    o[t]       = (a - mu) * rs * gamma[t]       + beta[t];
    o[t + 256] = (b - mu) * rs * gamma[t + 256] + beta[t + 256];
}

// ---------------- PE table ----------------
__global__ void pe_kernel(float* __restrict__ pe) {
    int idx = blockIdx.x * blockDim.x + threadIdx.x;
    if (idx >= LL * DD) return;
    int i = idx >> 9;
    int j = idx & 511;
    double freq  = exp(-2.0 * (double)j * log(10000.0) / 512.0);
    double angle = (double)(i - j) * freq;
    pe[idx] = ((j & 1) == 0) ? (float)cos(angle) : (float)sin(angle);
}

// ---------------- TF32 tensor-core GEMM: C[M,N] = A[M,K] * Bt[N,K]^T (+bias) ----
// Block tile 128x64, 256 threads, 8 warps as 4(m) x 2(n), warp tile 32x32.
// MODE 0: row-major C; MODE 1: scatter q/k/v; MODE 2: scatter g_pos.
#define GLD 36
template<int MODE>
__global__ void gemm_tc(const float* __restrict__ A, const float* __restrict__ Bt,
                        const float* __restrict__ bias, float* __restrict__ C,
                        int M, int N, int K) {
    __shared__ float As[128 * GLD];
    __shared__ float Bs[64 * GLD];
    int tid  = threadIdx.x, lane = tid & 31, warp = tid >> 5;
    int wm = warp >> 1, wn = warp & 1;
    int g  = lane >> 2, t4 = lane & 3;
    int bm = blockIdx.y * 128, bn = blockIdx.x * 64;

    float c[2][4][4];
    #pragma unroll
    for (int mt = 0; mt < 2; mt++)
        #pragma unroll
        for (int nt = 0; nt < 4; nt++)
            #pragma unroll
            for (int i = 0; i < 4; i++) c[mt][nt][i] = 0.f;

    for (int k0 = 0; k0 < K; k0 += 32) {
        for (int idx = tid; idx < 1024; idx += 256) {
            int r = idx >> 3, cc = (idx & 7) << 2;
            float4 v = *(const float4*)(A + (size_t)(bm + r) * K + k0 + cc);
            float4 w; w.x = f2tff(v.x); w.y = f2tff(v.y); w.z = f2tff(v.z); w.w = f2tff(v.w);
            *(float4*)(As + r * GLD + cc) = w;
        }
        for (int idx = tid; idx < 512; idx += 256) {
            int r = idx >> 3, cc = (idx & 7) << 2;
            float4 v = *(const float4*)(Bt + (size_t)(bn + r) * K + k0 + cc);
            float4 w; w.x = f2tff(v.x); w.y = f2tff(v.y); w.z = f2tff(v.z); w.w = f2tff(v.w);
            *(float4*)(Bs + r * GLD + cc) = w;
        }
        __syncthreads();
        #pragma unroll
        for (int kk = 0; kk < 32; kk += 8) {
            unsigned a[2][4], b[4][2];
            #pragma unroll
            for (int mt = 0; mt < 2; mt++) {
                const float* ap = As + (wm*32 + mt*16 + g) * GLD + kk + t4;
                a[mt][0] = __float_as_uint(ap[0]);
                a[mt][1] = __float_as_uint(ap[8 * GLD]);
                a[mt][2] = __float_as_uint(ap[4]);
                a[mt][3] = __float_as_uint(ap[8 * GLD + 4]);
            }
            #pragma unroll
            for (int nt = 0; nt < 4; nt++) {
                const float* bp = Bs + (wn*32 + nt*8 + g) * GLD + kk + t4;
                b[nt][0] = __float_as_uint(bp[0]);
                b[nt][1] = __float_as_uint(bp[4]);
            }
            #pragma unroll
            for (int mt = 0; mt < 2; mt++)
                #pragma unroll
                for (int nt = 0; nt < 4; nt++)
                    mma_tf32(c[mt][nt], a[mt], b[nt]);
        }
        __syncthreads();
    }

    // epilogue
    #pragma unroll
    for (int mt = 0; mt < 2; mt++) {
        #pragma unroll
        for (int nt = 0; nt < 4; nt++) {
            int r0 = bm + wm*32 + mt*16 + g;
            int c0 = bn + wn*32 + nt*8 + t4*2;
            #pragma unroll
            for (int e = 0; e < 4; e++) {
                int r = r0 + ((e >> 1) ? 8 : 0);
                int cc = c0 + (e & 1);
                float val = c[mt][nt][e] + (bias ? bias[cc] : 0.f);
                if (MODE == 0) {
                    C[(size_t)r * N + cc] = val;
                } else if (MODE == 1) {
                    int which = cc >> 9, rem = cc & 511;
                    int h = rem >> 6, dh = rem & 63;
                    int b_ = r >> 10, l = r & 1023;
                    float* dst = (which == 0) ? g_q : (which == 1) ? g_k : g_v;
                    dst[(((size_t)b_ * HH + h) * LL + l) * DH + dh] = val;
                } else {
                    int h = cc >> 6, dh = cc & 63;
                    g_pos[((size_t)h * LL + r) * DH + dh] = val;
                }
            }
        }
    }
}

// ---------------- flash attention with TF32 mma ----------------
// grid (L/64, B*H), 256 threads (8 warps: 4(m) x 2(n), warp tile 16x32).
// scores = [Q+u | Q+v] (64x128) . [K | P]^T (128x64), softmax, O += P.V
#define SA_LD 132
#define SB_LD 132
#define SV_LD 72
#define SC_LD 68
#define OFF_B  (64*SA_LD)
#define OFF_V  (OFF_B + 64*SB_LD)
#define OFF_SC (OFF_V + 64*SV_LD)
#define OFF_AL (OFF_SC + 64*SC_LD)
#define OFF_LI (OFF_AL + 64)
#define ATT_SMEM_FLOATS (OFF_LI + 64)

__global__ void attn_tc(const float* __restrict__ u_bias,
                        const float* __restrict__ v_bias) {
    extern __shared__ float sm[];
    float* sA     = sm;
    float* sB     = sm + OFF_B;
    float* sV     = sm + OFF_V;
    float* ssc    = sm + OFF_SC;
    float* salpha = sm + OFF_AL;
    float* sli    = sm + OFF_LI;

    int tid = threadIdx.x, lane = tid & 31, warp = tid >> 5;
    int wm = warp >> 1, wn = warp & 1;
    int g  = lane >> 2, t4 = lane & 3;
    int bh = blockIdx.y, b = bh >> 3, h = bh & 7;
    int q0 = blockIdx.x * 64;

    const float* qbase = g_q   + (size_t)bh * LL * DH;
    const float* kbase = g_k   + (size_t)bh * LL * DH;
    const float* vbase = g_v   + (size_t)bh * LL * DH;
    const float* pbase = g_pos + (size_t)h  * LL * DH;

    // load A tile: [Q+u | Q+v], tf32-rounded
    for (int idx = tid; idx < 1024; idx += 256) {
        int r = idx >> 4, c4 = (idx & 15) << 2;
        float4 q4 = *(const float4*)(qbase + (size_t)(q0 + r) * DH + c4);
        float4 u4 = *(const float4*)(u_bias + h * DH + c4);
        float4 v4 = *(const float4*)(v_bias + h * DH + c4);
        float4 w1; w1.x = f2tff(q4.x + u4.x); w1.y = f2tff(q4.y + u4.y);
                   w1.z = f2tff(q4.z + u4.z); w1.w = f2tff(q4.w + u4.w);
        float4 w2; w2.x = f2tff(q4.x + v4.x); w2.y = f2tff(q4.y + v4.y);
                   w2.z = f2tff(q4.z + v4.z); w2.w = f2tff(q4.w + v4.w);
        *(float4*)(sA + r * SA_LD + c4)      = w1;
        *(float4*)(sA + r * SA_LD + 64 + c4) = w2;
    }

    int srow = tid >> 2, ssub = tid & 3;
    float mi = -INFINITY, li = 0.f;
    float o[4][4];
    #pragma unroll
    for (int nt = 0; nt < 4; nt++)
        #pragma unroll
        for (int i = 0; i < 4; i++) o[nt][i] = 0.f;

    for (int kt = 0; kt < LL / 64; kt++) {
        __syncthreads();
        // load [K|P] and V tiles
        for (int idx = tid; idx < 1024; idx += 256) {
            int m = idx >> 4, c4 = (idx & 15) << 2;
            size_t go = (size_t)(kt * 64 + m) * DH + c4;
            float4 k4 = *(const float4*)(kbase + go);
            float4 p4 = *(const float4*)(pbase + go);
            float4 v4 = *(const float4*)(vbase + go);
            float4 wk; wk.x = f2tff(k4.x); wk.y = f2tff(k4.y); wk.z = f2tff(k4.z); wk.w = f2tff(k4.w);
            float4 wp; wp.x = f2tff(p4.x); wp.y = f2tff(p4.y); wp.z = f2tff(p4.z); wp.w = f2tff(p4.w);
            float4 wv; wv.x = f2tff(v4.x); wv.y = f2tff(v4.y); wv.z = f2tff(v4.z); wv.w = f2tff(v4.w);
            *(float4*)(sB + m * SB_LD + c4)      = wk;
            *(float4*)(sB + m * SB_LD + 64 + c4) = wp;
            *(float4*)(sV + m * SV_LD + c4)      = wv;
        }
        __syncthreads();

        // score mma: 64x64x128
        float s[4][4];
        #pragma unroll
        for (int nt = 0; nt < 4; nt++)
            #pragma unroll
            for (int i = 0; i < 4; i++) s[nt][i] = 0.f;
        #pragma unroll
        for (int kk = 0; kk < 128; kk += 8) {
            unsigned a[4];
            const float* ap = sA + (wm*16 + g) * SA_LD + kk + t4;
            a[0] = __float_as_uint(ap[0]);
            a[1] = __float_as_uint(ap[8 * SA_LD]);
            a[2] = __float_as_uint(ap[4]);
            a[3] = __float_as_uint(ap[8 * SA_LD + 4]);
            #pragma unroll
            for (int nt = 0; nt < 4; nt++) {
                unsigned bf[2];
                const float* bp = sB + (wn*32 + nt*8 + g) * SB_LD + kk + t4;
                bf[0] = __float_as_uint(bp[0]);
                bf[1] = __float_as_uint(bp[4]);
                mma_tf32(s[nt], a, bf);
            }
        }
        // scaled scores -> smem
        #pragma unroll
        for (int nt = 0; nt < 4; nt++) {
            float* d = ssc + (wm*16 + g) * SC_LD + wn*32 + nt*8 + t4*2;
            float2 lo; lo.x = s[nt][0] * 0.125f; lo.y = s[nt][1] * 0.125f;
            float2 hi; hi.x = s[nt][2] * 0.125f; hi.y = s[nt][3] * 0.125f;
            *(float2*)d              = lo;
            *(float2*)(d + 8*SC_LD)  = hi;
        }
        __syncthreads();

        // online softmax (4 threads per row)
        {
            float* rp = ssc + srow * SC_LD + ssub * 16;
            float tm = -INFINITY;
            #pragma unroll
            for (int i = 0; i < 16; i++) tm = fmaxf(tm, rp[i]);
            tm = fmaxf(tm, __shfl_xor_sync(0xffffffffu, tm, 1));
            tm = fmaxf(tm, __shfl_xor_sync(0xffffffffu, tm, 2));
            float newm = fmaxf(mi, tm);
            float alpha = expf(mi - newm);
            float ls = 0.f;
            #pragma unroll
            for (int i = 0; i < 16; i++) {
                float p = expf(rp[i] - newm);
                ls += p;
                rp[i] = f2tff(p);
            }
            ls += __shfl_xor_sync(0xffffffffu, ls, 1);
            ls += __shfl_xor_sync(0xffffffffu, ls, 2);
            li = li * alpha + ls;
            mi = newm;
            if (ssub == 0) salpha[srow] = alpha;
        }
        __syncthreads();

        // AV mma: O = O*alpha + P.V  (64x64x64)
        {
            float aa = salpha[wm*16 + g];
            float ab = salpha[wm*16 + g + 8];
            #pragma unroll
            for (int nt = 0; nt < 4; nt++) {
                o[nt][0] *= aa; o[nt][1] *= aa;
                o[nt][2] *= ab; o[nt][3] *= ab;
            }
            #pragma unroll
            for (int kk = 0; kk < 64; kk += 8) {
                unsigned a[4];
                const float* ap = ssc + (wm*16 + g) * SC_LD + kk + t4;
                a[0] = __float_as_uint(ap[0]);
                a[1] = __float_as_uint(ap[8 * SC_LD]);
                a[2] = __float_as_uint(ap[4]);
                a[3] = __float_as_uint(ap[8 * SC_LD + 4]);
                #pragma unroll
                for (int nt = 0; nt < 4; nt++) {
                    unsigned bf[2];
                    const float* bp = sV + (kk + t4) * SV_LD + wn*32 + nt*8 + g;
                    bf[0] = __float_as_uint(bp[0]);
                    bf[1] = __float_as_uint(bp[4 * SV_LD]);
                    mma_tf32(o[nt], a, bf);
                }
            }
        }
    }

    // finalize
    if (ssub == 0) sli[srow] = li;
    __syncthreads();
    float inva = 1.f / sli[wm*16 + g];
    float invb = 1.f / sli[wm*16 + g + 8];
    #pragma unroll
    for (int nt = 0; nt < 4; nt++) {
        int dh0 = wn*32 + nt*8 + t4*2;
        float* o1 = g_att + ((size_t)(b * LL + q0 + wm*16 + g))     * INNER + h * DH + dh0;
        float* o2 = g_att + ((size_t)(b * LL + q0 + wm*16 + g + 8)) * INNER + h * DH + dh0;
        o1[0] = o[nt][0] * inva; o1[1] = o[nt][1] * inva;
        o2[0] = o[nt][2] * invb; o2[1] = o[nt][3] * invb;
    }
}

// ---------------- launch ----------------
extern "C" void kernel_launch(void* const* d_in, const int* in_sizes, int n_in,
                              void* d_out, int out_size) {
    const float* x      = (const float*)d_in[0];
    const float* gamma  = (const float*)d_in[1];
    const float* beta   = (const float*)d_in[2];
    const float* w_qkv  = (const float*)d_in[3];
    const float* b_qkv  = (const float*)d_in[4];
    const float* w_pos  = (const float*)d_in[5];
    const float* w_out  = (const float*)d_in[6];
    const float* b_out  = (const float*)d_in[7];
    const float* u_bias = (const float*)d_in[8];
    const float* v_bias = (const float*)d_in[9];
    float* out = (float*)d_out;

    float *p_xn, *p_pe, *p_att;
    cudaGetSymbolAddress((void**)&p_xn,  g_xn);
    cudaGetSymbolAddress((void**)&p_pe,  g_pe);
    cudaGetSymbolAddress((void**)&p_att, g_att);

    // 1. LayerNorm
    ln_kernel<<<ROWS, 256>>>(x, gamma, beta, p_xn);

    // 2. PE table
    pe_kernel<<<(LL*DD + 255) / 256, 256>>>(p_pe);

    // 3. pos = PE @ w_pos^T -> g_pos
    {
        dim3 grid(INNER / 64, LL / 128);
        gemm_tc<2><<<grid, 256>>>(p_pe, w_pos, nullptr, nullptr, LL, INNER, DD);
    }

    // 4. QKV GEMM -> g_q/g_k/g_v
    {
        dim3 grid((3 * INNER) / 64, ROWS / 128);
        gemm_tc<1><<<grid, 256>>>(p_xn, w_qkv, b_qkv, nullptr, ROWS, 3 * INNER, DD);
    }

    // 5. attention
    {
        int smem = ATT_SMEM_FLOATS * (int)sizeof(float);   // ~104 KB
        cudaFuncSetAttribute(attn_tc, cudaFuncAttributeMaxDynamicSharedMemorySize, smem);
        dim3 grid(LL / 64, BB * HH);
        attn_tc<<<grid, 256, smem>>>(u_bias, v_bias);
    }

    // 6. out projection -> d_out
    {
        dim3 grid(DD / 64, ROWS / 128);
        gemm_tc<0><<<grid, 256>>>(p_att, w_out, b_out, out, ROWS, DD, INNER);
    }
}

// round 5
// speedup vs baseline: 4.1366x; 1.3326x over previous
#include <cuda_runtime.h>
#include <math.h>

// Problem constants
#define BB 8
#define LL 1024
#define DD 512
#define HH 8
#define DH 64
#define INNER 512
#define ROWS (BB*LL)          // 8192
#define EPSV 1e-5f

// ---------------- scratch (device globals; no allocation) ----------------
__device__ float  g_xn [ROWS*DD];
__device__ float  g_pe [LL*DD];
__device__ float  g_pos[HH*LL*DH];
__device__ float  g_q  [BB*HH*LL*DH];
__device__ float  g_k  [BB*HH*LL*DH];
__device__ float  g_v  [BB*HH*LL*DH];
__device__ float  g_att[ROWS*INNER];
__device__ double g_freq[DD];

// ---------------- tf32 + cp.async helpers ----------------
__device__ __forceinline__ unsigned f2tf(float x) {
    unsigned r; asm("cvt.rna.tf32.f32 %0, %1;" : "=r"(r) : "f"(x)); return r;
}
__device__ __forceinline__ float f2tff(float x) { return __uint_as_float(f2tf(x)); }

__device__ __forceinline__ void mma_tf32(float c[4], const unsigned a[4], const unsigned b[2]) {
    asm volatile(
        "mma.sync.aligned.m16n8k8.row.col.f32.tf32.tf32.f32 "
        "{%0,%1,%2,%3}, {%4,%5,%6,%7}, {%8,%9}, {%0,%1,%2,%3};"
        : "+f"(c[0]), "+f"(c[1]), "+f"(c[2]), "+f"(c[3])
        : "r"(a[0]), "r"(a[1]), "r"(a[2]), "r"(a[3]), "r"(b[0]), "r"(b[1]));
}

__device__ __forceinline__ void cpa16(float* dst_smem, const float* src) {
    unsigned d = (unsigned)__cvta_generic_to_shared(dst_smem);
    asm volatile("cp.async.cg.shared.global [%0], [%1], 16;" :: "r"(d), "l"(src));
}
#define CP_COMMIT asm volatile("cp.async.commit_group;")
#define CP_WAIT0  asm volatile("cp.async.wait_group 0;")

// ---------------- LayerNorm: one block per row ----------------
__global__ void ln_kernel(const float* __restrict__ x,
                          const float* __restrict__ gamma,
                          const float* __restrict__ beta,
                          float* __restrict__ xn) {
    int row = blockIdx.x;
    const float* xr = x + (size_t)row * DD;
    int t = threadIdx.x;                       // 256 threads
    float a = xr[t], b = xr[t + 256];
    float s = a + b, sq = a*a + b*b;
    #pragma unroll
    for (int o = 16; o; o >>= 1) {
        s  += __shfl_xor_sync(0xffffffffu, s,  o);
        sq += __shfl_xor_sync(0xffffffffu, sq, o);
    }
    __shared__ float ss[8], ssq[8];
    if ((t & 31) == 0) { ss[t >> 5] = s; ssq[t >> 5] = sq; }
    __syncthreads();
    float ts = 0.f, tsq = 0.f;
    #pragma unroll
    for (int i = 0; i < 8; i++) { ts += ss[i]; tsq += ssq[i]; }
    float mu  = ts * (1.f / DD);
    float var = fmaxf(tsq * (1.f / DD) - mu * mu, 0.f);
    float rs  = rsqrtf(var + EPSV);
    float* o = xn + (size_t)row * DD;
    o[t]       = (a - mu) * rs * gamma[t]       + beta[t];
    o[t + 256] = (b - mu) * rs * gamma[t + 256] + beta[t + 256];
}

// ---------------- PE: freq table (fp64, tiny) + fast sin/cos ----------------
__global__ void freq_kernel() {
    int j = threadIdx.x + blockIdx.x * blockDim.x;
    if (j < DD) g_freq[j] = exp(-(double)j * (log(10000.0) / 256.0));
}
__global__ void pe_kernel(float* __restrict__ pe) {
    int idx = blockIdx.x * blockDim.x + threadIdx.x;
    if (idx >= LL * DD) return;
    int i = idx >> 9;
    int j = idx & 511;
    double angle = (double)(i - j) * g_freq[j];
    double n = rint(angle * 0.15915494309189535);   // 1/(2*pi)
    double r = angle - n * 6.283185307179586;       // reduced to [-pi, pi]
    float rf = (float)r;
    pe[idx] = ((j & 1) == 0) ? cosf(rf) : sinf(rf);
}

// ---------------- TF32 TC GEMM, 128x128 tile, cp.async double buffer -------
// C[M,N] = A[M,K] * Bt[N,K]^T (+bias). 256 thr, 8 warps = 2(m) x 4(n),
// warp tile 64x32. K staged in chunks of 32, raw fp32 in smem, cvt at frag load.
// MODE 0: row-major C; MODE 1: scatter q/k/v; MODE 2: scatter g_pos.
#define GLD 36
#define GSTAGE (128 * GLD)
template<int MODE>
__global__ __launch_bounds__(256) void gemm_tc(const float* __restrict__ A,
                        const float* __restrict__ Bt,
                        const float* __restrict__ bias, float* __restrict__ C,
                        int M, int N, int K) {
    __shared__ float As[2 * GSTAGE];
    __shared__ float Bs[2 * GSTAGE];
    int tid  = threadIdx.x, lane = tid & 31, warp = tid >> 5;
    int wm = warp >> 2, wn = warp & 3;
    int g  = lane >> 2, t4 = lane & 3;
    int bm = blockIdx.y * 128, bn = blockIdx.x * 128;

    float c[4][4][4];
    #pragma unroll
    for (int mt = 0; mt < 4; mt++)
        #pragma unroll
        for (int nt = 0; nt < 4; nt++)
            #pragma unroll
            for (int i = 0; i < 4; i++) c[mt][nt][i] = 0.f;

    int nstg = K >> 5;   // K/32
    int ldr = tid >> 1, ldc = (tid & 1) << 4;   // 256 thr -> 128 rows x 2 cols(16)
    // prologue: stage 0
    {
        const float* a0 = A  + (size_t)(bm + ldr) * K + ldc;
        const float* b0 = Bt + (size_t)(bn + ldr) * K + ldc;
        float* da = As + ldr * GLD + ldc;
        float* db = Bs + ldr * GLD + ldc;
        cpa16(da, a0); cpa16(da + 4, a0 + 4); cpa16(da + 8, a0 + 8); cpa16(da + 12, a0 + 12);
        cpa16(db, b0); cpa16(db + 4, b0 + 4); cpa16(db + 8, b0 + 8); cpa16(db + 12, b0 + 12);
        CP_COMMIT;
    }
    for (int s = 0; s < nstg; s++) {
        CP_WAIT0; __syncthreads();
        if (s + 1 < nstg) {
            int buf = (s + 1) & 1, k0 = (s + 1) << 5;
            const float* a0 = A  + (size_t)(bm + ldr) * K + k0 + ldc;
            const float* b0 = Bt + (size_t)(bn + ldr) * K + k0 + ldc;
            float* da = As + buf * GSTAGE + ldr * GLD + ldc;
            float* db = Bs + buf * GSTAGE + ldr * GLD + ldc;
            cpa16(da, a0); cpa16(da + 4, a0 + 4); cpa16(da + 8, a0 + 8); cpa16(da + 12, a0 + 12);
            cpa16(db, b0); cpa16(db + 4, b0 + 4); cpa16(db + 8, b0 + 8); cpa16(db + 12, b0 + 12);
            CP_COMMIT;
        }
        const float* Ab = As + (s & 1) * GSTAGE;
        const float* Bb = Bs + (s & 1) * GSTAGE;
        #pragma unroll
        for (int kk = 0; kk < 32; kk += 8) {
            unsigned a[4][4], b[4][2];
            #pragma unroll
            for (int mt = 0; mt < 4; mt++) {
                const float* ap = Ab + (wm*64 + mt*16 + g) * GLD + kk + t4;
                a[mt][0] = f2tf(ap[0]);
                a[mt][1] = f2tf(ap[8 * GLD]);
                a[mt][2] = f2tf(ap[4]);
                a[mt][3] = f2tf(ap[8 * GLD + 4]);
            }
            #pragma unroll
            for (int nt = 0; nt < 4; nt++) {
                const float* bp = Bb + (wn*32 + nt*8 + g) * GLD + kk + t4;
                b[nt][0] = f2tf(bp[0]);
                b[nt][1] = f2tf(bp[4]);
            }
            #pragma unroll
            for (int mt = 0; mt < 4; mt++)
                #pragma unroll
                for (int nt = 0; nt < 4; nt++)
                    mma_tf32(c[mt][nt], a[mt], b[nt]);
        }
        __syncthreads();
    }

    // epilogue
    #pragma unroll
    for (int mt = 0; mt < 4; mt++) {
        #pragma unroll
        for (int nt = 0; nt < 4; nt++) {
            int r0 = bm + wm*64 + mt*16 + g;
            int c0 = bn + wn*32 + nt*8 + t4*2;
            #pragma unroll
            for (int e = 0; e < 4; e++) {
                int r = r0 + ((e >> 1) ? 8 : 0);
                int cc = c0 + (e & 1);
                float val = c[mt][nt][e] + (bias ? bias[cc] : 0.f);
                if (MODE == 0) {
                    C[(size_t)r * N + cc] = val;
                } else if (MODE == 1) {
                    int which = cc >> 9, rem = cc & 511;
                    int h = rem >> 6, dh = rem & 63;
                    int b_ = r >> 10, l = r & 1023;
                    float* dst = (which == 0) ? g_q : (which == 1) ? g_k : g_v;
                    dst[(((size_t)b_ * HH + h) * LL + l) * DH + dh] = val;
                } else {
                    int h = cc >> 6, dh = cc & 63;
                    g_pos[((size_t)h * LL + r) * DH + dh] = val;
                }
            }
        }
    }
}

// ---------------- flash attention, TF32 mma, cp.async double buffer --------
// Q-tile 128 rows, KV-tile 64 keys, 256 thr (8 warps = 4(m) x 2(n), 32x32).
// scores = [Q+u | Q+v](128x128) . [K | P]^T, online softmax, O += P.V
#define SA_LD  132
#define SKP_LD 132
#define SV_LD  72
#define SC_LD  68
#define AT_OFF_KP  (128 * SA_LD)
#define AT_OFF_V   (AT_OFF_KP + 2 * 64 * SKP_LD)
#define AT_OFF_SC  (AT_OFF_V  + 2 * 64 * SV_LD)
#define AT_OFF_AL  (AT_OFF_SC + 128 * SC_LD)
#define AT_OFF_LI  (AT_OFF_AL + 128)
#define AT_SMEM_FLOATS (AT_OFF_LI + 128)

__global__ __launch_bounds__(256) void attn_tc(const float* __restrict__ u_bias,
                                               const float* __restrict__ v_bias) {
    extern __shared__ float sm[];
    float* sA  = sm;
    float* sKP = sm + AT_OFF_KP;
    float* sV  = sm + AT_OFF_V;
    float* ssc = sm + AT_OFF_SC;
    float* sal = sm + AT_OFF_AL;
    float* sli = sm + AT_OFF_LI;

    int tid = threadIdx.x, lane = tid & 31, warp = tid >> 5;
    int wm = warp >> 1, wn = warp & 1;
    int g  = lane >> 2, t4 = lane & 3;
    int bh = blockIdx.y, b = bh >> 3, h = bh & 7;
    int q0 = blockIdx.x * 128;

    const float* qb = g_q   + (size_t)bh * LL * DH;
    const float* kb = g_k   + (size_t)bh * LL * DH;
    const float* vb = g_v   + (size_t)bh * LL * DH;
    const float* pb = g_pos + (size_t)h  * LL * DH;

    // prologue: stage 0 of K|P and V
    for (int idx = tid; idx < 1024; idx += 256) {
        int m = idx >> 4, c4 = (idx & 15) << 2;
        size_t go = (size_t)m * DH + c4;
        cpa16(sKP + m * SKP_LD + c4,      kb + go);
        cpa16(sKP + m * SKP_LD + 64 + c4, pb + go);
        cpa16(sV  + m * SV_LD  + c4,      vb + go);
    }
    CP_COMMIT;

    // build sA = [Q+u | Q+v] tf32-rounded (overlaps stage-0 loads)
    for (int idx = tid; idx < 2048; idx += 256) {
        int r = idx >> 4, c4 = (idx & 15) << 2;
        float4 q4 = *(const float4*)(qb + (size_t)(q0 + r) * DH + c4);
        float4 u4 = *(const float4*)(u_bias + h * DH + c4);
        float4 v4 = *(const float4*)(v_bias + h * DH + c4);
        float4 w1; w1.x = f2tff(q4.x + u4.x); w1.y = f2tff(q4.y + u4.y);
                   w1.z = f2tff(q4.z + u4.z); w1.w = f2tff(q4.w + u4.w);
        float4 w2; w2.x = f2tff(q4.x + v4.x); w2.y = f2tff(q4.y + v4.y);
                   w2.z = f2tff(q4.z + v4.z); w2.w = f2tff(q4.w + v4.w);
        *(float4*)(sA + r * SA_LD + c4)      = w1;
        *(float4*)(sA + r * SA_LD + 64 + c4) = w2;
    }

    int srow = tid >> 1, ssub = tid & 1;    // softmax: 2 threads per row, 32 cols each
    float mi = -INFINITY, li = 0.f;
    float o[2][4][4];
    #pragma unroll
    for (int mt = 0; mt < 2; mt++)
        #pragma unroll
        for (int nt = 0; nt < 4; nt++)
            #pragma unroll
            for (int i = 0; i < 4; i++) o[mt][nt][i] = 0.f;

    for (int kt = 0; kt < LL / 64; kt++) {
        CP_WAIT0;
        __syncthreads();
        int cur = kt & 1;
        if (kt + 1 < LL / 64) {
            int nb = (kt + 1) & 1;
            float* dKP = sKP + nb * 64 * SKP_LD;
            float* dV  = sV  + nb * 64 * SV_LD;
            for (int idx = tid; idx < 1024; idx += 256) {
                int m = idx >> 4, c4 = (idx & 15) << 2;
                size_t go = (size_t)((kt + 1) * 64 + m) * DH + c4;
                cpa16(dKP + m * SKP_LD + c4,      kb + go);
                cpa16(dKP + m * SKP_LD + 64 + c4, pb + go);
                cpa16(dV  + m * SV_LD  + c4,      vb + go);
            }
            CP_COMMIT;
        }
        const float* KPb = sKP + cur * 64 * SKP_LD;
        const float* Vb  = sV  + cur * 64 * SV_LD;

        // scores: 128x64 C, K=128
        float s[2][4][4];
        #pragma unroll
        for (int mt = 0; mt < 2; mt++)
            #pragma unroll
            for (int nt = 0; nt < 4; nt++)
                #pragma unroll
                for (int i = 0; i < 4; i++) s[mt][nt][i] = 0.f;
        #pragma unroll
        for (int kk = 0; kk < 128; kk += 8) {
            unsigned a[2][4], bf[4][2];
            #pragma unroll
            for (int mt = 0; mt < 2; mt++) {
                const float* ap = sA + (wm*32 + mt*16 + g) * SA_LD + kk + t4;
                a[mt][0] = __float_as_uint(ap[0]);
                a[mt][1] = __float_as_uint(ap[8 * SA_LD]);
                a[mt][2] = __float_as_uint(ap[4]);
                a[mt][3] = __float_as_uint(ap[8 * SA_LD + 4]);
            }
            #pragma unroll
            for (int nt = 0; nt < 4; nt++) {
                const float* bp = KPb + (wn*32 + nt*8 + g) * SKP_LD + kk + t4;
                bf[nt][0] = f2tf(bp[0]);
                bf[nt][1] = f2tf(bp[4]);
            }
            #pragma unroll
            for (int mt = 0; mt < 2; mt++)
                #pragma unroll
                for (int nt = 0; nt < 4; nt++)
                    mma_tf32(s[mt][nt], a[mt], bf[nt]);
        }
        #pragma unroll
        for (int mt = 0; mt < 2; mt++)
            #pragma unroll
            for (int nt = 0; nt < 4; nt++) {
                float* d = ssc + (wm*32 + mt*16 + g) * SC_LD + wn*32 + nt*8 + t4*2;
                float2 lo; lo.x = s[mt][nt][0] * 0.125f; lo.y = s[mt][nt][1] * 0.125f;
                float2 hi; hi.x = s[mt][nt][2] * 0.125f; hi.y = s[mt][nt][3] * 0.125f;
                *(float2*)d             = lo;
                *(float2*)(d + 8*SC_LD) = hi;
            }
        __syncthreads();

        // online softmax (2 threads per row, 32 scores each)
        {
            float* rp = ssc + srow * SC_LD + ssub * 32;
            float tm = -INFINITY;
            #pragma unroll
            for (int i = 0; i < 32; i++) tm = fmaxf(tm, rp[i]);
            tm = fmaxf(tm, __shfl_xor_sync(0xffffffffu, tm, 1));
            float newm = fmaxf(mi, tm);
            float alpha = __expf(mi - newm);
            float ls = 0.f;
            #pragma unroll
            for (int i = 0; i < 32; i++) {
                float p = __expf(rp[i] - newm);
                ls += p;
                rp[i] = f2tff(p);
            }
            ls += __shfl_xor_sync(0xffffffffu, ls, 1);
            li = li * alpha + ls;
            mi = newm;
            if (ssub == 0) sal[srow] = alpha;
        }
        __syncthreads();

        // AV: O = O*alpha + P.V  (128x64 C, K=64)
        {
            #pragma unroll
            for (int mt = 0; mt < 2; mt++) {
                float aa = sal[wm*32 + mt*16 + g];
                float ab = sal[wm*32 + mt*16 + g + 8];
                #pragma unroll
                for (int nt = 0; nt < 4; nt++) {
                    o[mt][nt][0] *= aa; o[mt][nt][1] *= aa;
                    o[mt][nt][2] *= ab; o[mt][nt][3] *= ab;
                }
            }
            #pragma unroll
            for (int kk = 0; kk < 64; kk += 8) {
                unsigned a[2][4], bf[4][2];
                #pragma unroll
                for (int mt = 0; mt < 2; mt++) {
                    const float* ap = ssc + (wm*32 + mt*16 + g) * SC_LD + kk + t4;
                    a[mt][0] = __float_as_uint(ap[0]);
                    a[mt][1] = __float_as_uint(ap[8 * SC_LD]);
                    a[mt][2] = __float_as_uint(ap[4]);
                    a[mt][3] = __float_as_uint(ap[8 * SC_LD + 4]);
                }
                #pragma unroll
                for (int nt = 0; nt < 4; nt++) {
                    const float* bp = Vb + (kk + t4) * SV_LD + wn*32 + nt*8 + g;
                    bf[nt][0] = f2tf(bp[0]);
                    bf[nt][1] = f2tf(bp[4 * SV_LD]);
                }
                #pragma unroll
                for (int mt = 0; mt < 2; mt++)
                    #pragma unroll
                    for (int nt = 0; nt < 4; nt++)
                        mma_tf32(o[mt][nt], a[mt], bf[nt]);
            }
        }
        // next iteration's top sync guards buffer/ssc reuse
    }

    // finalize
    if (ssub == 0) sli[srow] = li;
    __syncthreads();
    #pragma unroll
    for (int mt = 0; mt < 2; mt++) {
        int r0 = wm*32 + mt*16 + g;
        float inva = 1.f / sli[r0];
        float invb = 1.f / sli[r0 + 8];
        #pragma unroll
        for (int nt = 0; nt < 4; nt++) {
            int dh0 = wn*32 + nt*8 + t4*2;
            float* o1 = g_att + ((size_t)(b * LL + q0 + r0))     * INNER + h * DH + dh0;
            float* o2 = g_att + ((size_t)(b * LL + q0 + r0 + 8)) * INNER + h * DH + dh0;
            o1[0] = o[mt][nt][0] * inva; o1[1] = o[mt][nt][1] * inva;
            o2[0] = o[mt][nt][2] * invb; o2[1] = o[mt][nt][3] * invb;
        }
    }
}

// ---------------- launch ----------------
extern "C" void kernel_launch(void* const* d_in, const int* in_sizes, int n_in,
                              void* d_out, int out_size) {
    const float* x      = (const float*)d_in[0];
    const float* gamma  = (const float*)d_in[1];
    const float* beta   = (const float*)d_in[2];
    const float* w_qkv  = (const float*)d_in[3];
    const float* b_qkv  = (const float*)d_in[4];
    const float* w_pos  = (const float*)d_in[5];
    const float* w_out  = (const float*)d_in[6];
    const float* b_out  = (const float*)d_in[7];
    const float* u_bias = (const float*)d_in[8];
    const float* v_bias = (const float*)d_in[9];
    float* out = (float*)d_out;

    float *p_xn, *p_pe, *p_att;
    cudaGetSymbolAddress((void**)&p_xn,  g_xn);
    cudaGetSymbolAddress((void**)&p_pe,  g_pe);
    cudaGetSymbolAddress((void**)&p_att, g_att);

    // 1. LayerNorm
    ln_kernel<<<ROWS, 256>>>(x, gamma, beta, p_xn);

    // 2. PE table (freq table then fast sin/cos)
    freq_kernel<<<2, 256>>>();
    pe_kernel<<<(LL*DD + 255) / 256, 256>>>(p_pe);

    // 3. pos = PE @ w_pos^T -> g_pos
    {
        dim3 grid(INNER / 128, LL / 128);
        gemm_tc<2><<<grid, 256>>>(p_pe, w_pos, nullptr, nullptr, LL, INNER, DD);
    }

    // 4. QKV GEMM -> g_q/g_k/g_v
    {
        dim3 grid((3 * INNER) / 128, ROWS / 128);
        gemm_tc<1><<<grid, 256>>>(p_xn, w_qkv, b_qkv, nullptr, ROWS, 3 * INNER, DD);
    }

    // 5. attention
    {
        int smem = AT_SMEM_FLOATS * (int)sizeof(float);   // ~208 KB
        cudaFuncSetAttribute(attn_tc, cudaFuncAttributeMaxDynamicSharedMemorySize, smem);
        dim3 grid(LL / 128, BB * HH);
        attn_tc<<<grid, 256, smem>>>(u_bias, v_bias);
    }

    // 6. out projection -> d_out
    {
        dim3 grid(DD / 128, ROWS / 128);
        gemm_tc<0><<<grid, 256>>>(p_att, w_out, b_out, out, ROWS, DD, INNER);
    }
}

// round 6
// speedup vs baseline: 4.3074x; 1.0413x over previous
#include <cuda_runtime.h>
#include <math.h>

// Problem constants
#define BB 8
#define LL 1024
#define DD 512
#define HH 8
#define DH 64
#define INNER 512
#define ROWS (BB*LL)          // 8192
#define EPSV 1e-5f

// ---------------- scratch (device globals; no allocation) ----------------
__device__ float  g_xn [ROWS*DD];
__device__ float  g_pe [LL*DD];
__device__ float  g_pos[HH*LL*DH];
__device__ float  g_q  [BB*HH*LL*DH];
__device__ float  g_k  [BB*HH*LL*DH];
__device__ float  g_v  [BB*HH*LL*DH];
__device__ float  g_att[ROWS*INNER];
__device__ float  g_wqkv[3*INNER*DD];
__device__ float  g_wpos[INNER*DD];
__device__ float  g_wout[DD*INNER];
__device__ double g_freq[DD];

// ---------------- tf32 + cp.async helpers ----------------
__device__ __forceinline__ unsigned f2tf(float x) {
    unsigned r; asm("cvt.rna.tf32.f32 %0, %1;" : "=r"(r) : "f"(x)); return r;
}
__device__ __forceinline__ float f2tff(float x) { return __uint_as_float(f2tf(x)); }

__device__ __forceinline__ void mma_tf32(float c[4], const unsigned a[4], const unsigned b[2]) {
    asm volatile(
        "mma.sync.aligned.m16n8k8.row.col.f32.tf32.tf32.f32 "
        "{%0,%1,%2,%3}, {%4,%5,%6,%7}, {%8,%9}, {%0,%1,%2,%3};"
        : "+f"(c[0]), "+f"(c[1]), "+f"(c[2]), "+f"(c[3])
        : "r"(a[0]), "r"(a[1]), "r"(a[2]), "r"(a[3]), "r"(b[0]), "r"(b[1]));
}

__device__ __forceinline__ void cpa16(float* dst_smem, const float* src) {
    unsigned d = (unsigned)__cvta_generic_to_shared(dst_smem);
    asm volatile("cp.async.cg.shared.global [%0], [%1], 16;" :: "r"(d), "l"(src));
}
#define CP_COMMIT asm volatile("cp.async.commit_group;")
#define CP_WAIT0  asm volatile("cp.async.wait_group 0;")

// ---------------- round weights to tf32 (once per call, tiny) -------------
__global__ void round_w(const float* __restrict__ wq, const float* __restrict__ wp,
                        const float* __restrict__ wo) {
    const int n1 = 3*INNER*DD/4, n2 = INNER*DD/4, n3 = DD*INNER/4;
    int i = blockIdx.x * blockDim.x + threadIdx.x;
    float4 v; float4* dst;
    if (i < n1) {
        v = ((const float4*)wq)[i]; dst = ((float4*)g_wqkv) + i;
    } else if (i < n1 + n2) {
        v = ((const float4*)wp)[i - n1]; dst = ((float4*)g_wpos) + (i - n1);
    } else if (i < n1 + n2 + n3) {
        v = ((const float4*)wo)[i - n1 - n2]; dst = ((float4*)g_wout) + (i - n1 - n2);
    } else return;
    float4 w; w.x = f2tff(v.x); w.y = f2tff(v.y); w.z = f2tff(v.z); w.w = f2tff(v.w);
    *dst = w;
}

// ---------------- freq table (fp64, tiny) ----------------
__global__ void freq_kernel() {
    int j = threadIdx.x + blockIdx.x * blockDim.x;
    if (j < DD) g_freq[j] = exp(-(double)j * (log(10000.0) / 256.0));
}

// ---------------- fused LayerNorm + PE table ----------------
__global__ void ln_pe_kernel(const float* __restrict__ x,
                             const float* __restrict__ gamma,
                             const float* __restrict__ beta,
                             float* __restrict__ xn,
                             float* __restrict__ pe) {
    if (blockIdx.x < ROWS) {
        int row = blockIdx.x;
        const float* xr = x + (size_t)row * DD;
        int t = threadIdx.x;                       // 256 threads
        float a = xr[t], b = xr[t + 256];
        float s = a + b, sq = a*a + b*b;
        #pragma unroll
        for (int o = 16; o; o >>= 1) {
            s  += __shfl_xor_sync(0xffffffffu, s,  o);
            sq += __shfl_xor_sync(0xffffffffu, sq, o);
        }
        __shared__ float ss[8], ssq[8];
        if ((t & 31) == 0) { ss[t >> 5] = s; ssq[t >> 5] = sq; }
        __syncthreads();
        float ts = 0.f, tsq = 0.f;
        #pragma unroll
        for (int i = 0; i < 8; i++) { ts += ss[i]; tsq += ssq[i]; }
        float mu  = ts * (1.f / DD);
        float var = fmaxf(tsq * (1.f / DD) - mu * mu, 0.f);
        float rs  = rsqrtf(var + EPSV);
        float* o = xn + (size_t)row * DD;
        o[t]       = f2tff((a - mu) * rs * gamma[t]       + beta[t]);
        o[t + 256] = f2tff((b - mu) * rs * gamma[t + 256] + beta[t + 256]);
    } else {
        int idx = (blockIdx.x - ROWS) * 256 + threadIdx.x;
        if (idx >= LL * DD) return;
        int i = idx >> 9;
        int j = idx & 511;
        double angle = (double)(i - j) * g_freq[j];
        double n = rint(angle * 0.15915494309189535);   // 1/(2*pi)
        double r = angle - n * 6.283185307179586;       // reduced to [-pi, pi]
        float rf = (float)r;
        pe[idx] = f2tff(((j & 1) == 0) ? cosf(rf) : sinf(rf));
    }
}

// ---------------- TF32 TC GEMM body, 128x128 tile, cp.async double buffer --
// All operands pre-rounded to tf32; fragment loads are plain LDS.
// MODE 0: row-major C; MODE 1: scatter q/k/v; MODE 2: scatter g_pos.
#define GLD 36
#define GSTAGE (128 * GLD)
template<int MODE>
__device__ __forceinline__ void gemm_body(float* As, float* Bs,
                        const float* __restrict__ A, const float* __restrict__ Bt,
                        const float* __restrict__ bias, float* __restrict__ C,
                        int M, int N, int K, int bxx, int byy) {
    int tid  = threadIdx.x, lane = tid & 31, warp = tid >> 5;
    int wm = warp >> 2, wn = warp & 3;
    int g  = lane >> 2, t4 = lane & 3;
    int bm = byy * 128, bn = bxx * 128;

    float c[4][4][4];
    #pragma unroll
    for (int mt = 0; mt < 4; mt++)
        #pragma unroll
        for (int nt = 0; nt < 4; nt++)
            #pragma unroll
            for (int i = 0; i < 4; i++) c[mt][nt][i] = 0.f;

    int nstg = K >> 5;   // K/32
    int ldr = tid >> 1, ldc = (tid & 1) << 4;   // 256 thr -> 128 rows x 2 cols(16)
    {
        const float* a0 = A  + (size_t)(bm + ldr) * K + ldc;
        const float* b0 = Bt + (size_t)(bn + ldr) * K + ldc;
        float* da = As + ldr * GLD + ldc;
        float* db = Bs + ldr * GLD + ldc;
        cpa16(da, a0); cpa16(da + 4, a0 + 4); cpa16(da + 8, a0 + 8); cpa16(da + 12, a0 + 12);
        cpa16(db, b0); cpa16(db + 4, b0 + 4); cpa16(db + 8, b0 + 8); cpa16(db + 12, b0 + 12);
        CP_COMMIT;
    }
    for (int s = 0; s < nstg; s++) {
        CP_WAIT0; __syncthreads();
        if (s + 1 < nstg) {
            int buf = (s + 1) & 1, k0 = (s + 1) << 5;
            const float* a0 = A  + (size_t)(bm + ldr) * K + k0 + ldc;
            const float* b0 = Bt + (size_t)(bn + ldr) * K + k0 + ldc;
            float* da = As + buf * GSTAGE + ldr * GLD + ldc;
            float* db = Bs + buf * GSTAGE + ldr * GLD + ldc;
            cpa16(da, a0); cpa16(da + 4, a0 + 4); cpa16(da + 8, a0 + 8); cpa16(da + 12, a0 + 12);
            cpa16(db, b0); cpa16(db + 4, b0 + 4); cpa16(db + 8, b0 + 8); cpa16(db + 12, b0 + 12);
            CP_COMMIT;
        }
        const float* Ab = As + (s & 1) * GSTAGE;
        const float* Bb = Bs + (s & 1) * GSTAGE;
        #pragma unroll
        for (int kk = 0; kk < 32; kk += 8) {
            unsigned a[4][4], b[4][2];
            #pragma unroll
            for (int mt = 0; mt < 4; mt++) {
                const float* ap = Ab + (wm*64 + mt*16 + g) * GLD + kk + t4;
                a[mt][0] = __float_as_uint(ap[0]);
                a[mt][1] = __float_as_uint(ap[8 * GLD]);
                a[mt][2] = __float_as_uint(ap[4]);
                a[mt][3] = __float_as_uint(ap[8 * GLD + 4]);
            }
            #pragma unroll
            for (int nt = 0; nt < 4; nt++) {
                const float* bp = Bb + (wn*32 + nt*8 + g) * GLD + kk + t4;
                b[nt][0] = __float_as_uint(bp[0]);
                b[nt][1] = __float_as_uint(bp[4]);
            }
            #pragma unroll
            for (int mt = 0; mt < 4; mt++)
                #pragma unroll
                for (int nt = 0; nt < 4; nt++)
                    mma_tf32(c[mt][nt], a[mt], b[nt]);
        }
        __syncthreads();
    }

    // epilogue
    #pragma unroll
    for (int mt = 0; mt < 4; mt++) {
        #pragma unroll
        for (int nt = 0; nt < 4; nt++) {
            int r0 = bm + wm*64 + mt*16 + g;
            int c0 = bn + wn*32 + nt*8 + t4*2;
            #pragma unroll
            for (int e = 0; e < 4; e++) {
                int r = r0 + ((e >> 1) ? 8 : 0);
                int cc = c0 + (e & 1);
                float val = c[mt][nt][e] + (bias ? bias[cc] : 0.f);
                if (MODE == 0) {
                    C[(size_t)r * N + cc] = val;            // final output: full fp32
                } else if (MODE == 1) {
                    int which = cc >> 9, rem = cc & 511;
                    int h = rem >> 6, dh = rem & 63;
                    int b_ = r >> 10, l = r & 1023;
                    float* dst = (which == 0) ? g_q : (which == 1) ? g_k : g_v;
                    dst[(((size_t)b_ * HH + h) * LL + l) * DH + dh] = f2tff(val);
                } else {
                    int h = cc >> 6, dh = cc & 63;
                    g_pos[((size_t)h * LL + r) * DH + dh] = f2tff(val);
                }
            }
        }
    }
}

// fused QKV + pos GEMM (z=0: QKV, z=1: pos) — fills the chip in one launch
__global__ __launch_bounds__(256) void gemm_fused(const float* __restrict__ b_qkv) {
    __shared__ float As[2 * GSTAGE];
    __shared__ float Bs[2 * GSTAGE];
    if (blockIdx.z == 0) {
        gemm_body<1>(As, Bs, g_xn, g_wqkv, b_qkv, nullptr, ROWS, 3*INNER, DD,
                     blockIdx.x, blockIdx.y);
    } else {
        if (blockIdx.x >= INNER/128 || blockIdx.y >= LL/128) return;
        gemm_body<2>(As, Bs, g_pe, g_wpos, nullptr, nullptr, LL, INNER, DD,
                     blockIdx.x, blockIdx.y);
    }
}

// out projection
__global__ __launch_bounds__(256) void gemm_out(const float* __restrict__ b_out,
                                                float* __restrict__ out) {
    __shared__ float As[2 * GSTAGE];
    __shared__ float Bs[2 * GSTAGE];
    gemm_body<0>(As, Bs, g_att, g_wout, b_out, out, ROWS, DD, INNER,
                 blockIdx.x, blockIdx.y);
}

// ---------------- flash attention, TF32 mma, cp.async double buffer --------
// Q-tile 128 rows, KV-tile 64 keys, 256 thr (8 warps = 4(m) x 2(n), 32x32).
// All global operands pre-rounded to tf32.
#define SA_LD  132
#define SKP_LD 132
#define SV_LD  72
#define SC_LD  68
#define AT_OFF_KP  (128 * SA_LD)
#define AT_OFF_V   (AT_OFF_KP + 2 * 64 * SKP_LD)
#define AT_OFF_SC  (AT_OFF_V  + 2 * 64 * SV_LD)
#define AT_OFF_AL  (AT_OFF_SC + 128 * SC_LD)
#define AT_OFF_LI  (AT_OFF_AL + 128)
#define AT_SMEM_FLOATS (AT_OFF_LI + 128)

__global__ __launch_bounds__(256) void attn_tc(const float* __restrict__ u_bias,
                                               const float* __restrict__ v_bias) {
    extern __shared__ float sm[];
    float* sA  = sm;
    float* sKP = sm + AT_OFF_KP;
    float* sV  = sm + AT_OFF_V;
    float* ssc = sm + AT_OFF_SC;
    float* sal = sm + AT_OFF_AL;
    float* sli = sm + AT_OFF_LI;

    int tid = threadIdx.x, lane = tid & 31, warp = tid >> 5;
    int wm = warp >> 1, wn = warp & 1;
    int g  = lane >> 2, t4 = lane & 3;
    int bh = blockIdx.y, b = bh >> 3, h = bh & 7;
    int q0 = blockIdx.x * 128;

    const float* qb = g_q   + (size_t)bh * LL * DH;
    const float* kb = g_k   + (size_t)bh * LL * DH;
    const float* vb = g_v   + (size_t)bh * LL * DH;
    const float* pb = g_pos + (size_t)h  * LL * DH;

    // prologue: stage 0 of K|P and V
    for (int idx = tid; idx < 1024; idx += 256) {
        int m = idx >> 4, c4 = (idx & 15) << 2;
        size_t go = (size_t)m * DH + c4;
        cpa16(sKP + m * SKP_LD + c4,      kb + go);
        cpa16(sKP + m * SKP_LD + 64 + c4, pb + go);
        cpa16(sV  + m * SV_LD  + c4,      vb + go);
    }
    CP_COMMIT;

    // build sA = [Q+u | Q+v] tf32-rounded
    for (int idx = tid; idx < 2048; idx += 256) {
        int r = idx >> 4, c4 = (idx & 15) << 2;
        float4 q4 = *(const float4*)(qb + (size_t)(q0 + r) * DH + c4);
        float4 u4 = *(const float4*)(u_bias + h * DH + c4);
        float4 v4 = *(const float4*)(v_bias + h * DH + c4);
        float4 w1; w1.x = f2tff(q4.x + u4.x); w1.y = f2tff(q4.y + u4.y);
                   w1.z = f2tff(q4.z + u4.z); w1.w = f2tff(q4.w + u4.w);
        float4 w2; w2.x = f2tff(q4.x + v4.x); w2.y = f2tff(q4.y + v4.y);
                   w2.z = f2tff(q4.z + v4.z); w2.w = f2tff(q4.w + v4.w);
        *(float4*)(sA + r * SA_LD + c4)      = w1;
        *(float4*)(sA + r * SA_LD + 64 + c4) = w2;
    }

    int srow = tid >> 1, ssub = tid & 1;    // softmax: 2 threads per row, 32 cols each
    float mi = -INFINITY, li = 0.f;
    float o[2][4][4];
    #pragma unroll
    for (int mt = 0; mt < 2; mt++)
        #pragma unroll
        for (int nt = 0; nt < 4; nt++)
            #pragma unroll
            for (int i = 0; i < 4; i++) o[mt][nt][i] = 0.f;

    for (int kt = 0; kt < LL / 64; kt++) {
        CP_WAIT0;
        __syncthreads();
        int cur = kt & 1;
        if (kt + 1 < LL / 64) {
            int nb = (kt + 1) & 1;
            float* dKP = sKP + nb * 64 * SKP_LD;
            float* dV  = sV  + nb * 64 * SV_LD;
            for (int idx = tid; idx < 1024; idx += 256) {
                int m = idx >> 4, c4 = (idx & 15) << 2;
                size_t go = (size_t)((kt + 1) * 64 + m) * DH + c4;
                cpa16(dKP + m * SKP_LD + c4,      kb + go);
                cpa16(dKP + m * SKP_LD + 64 + c4, pb + go);
                cpa16(dV  + m * SV_LD  + c4,      vb + go);
            }
            CP_COMMIT;
        }
        const float* KPb = sKP + cur * 64 * SKP_LD;
        const float* Vb  = sV  + cur * 64 * SV_LD;

        // scores: 128x64 C, K=128
        float s[2][4][4];
        #pragma unroll
        for (int mt = 0; mt < 2; mt++)
            #pragma unroll
            for (int nt = 0; nt < 4; nt++)
                #pragma unroll
                for (int i = 0; i < 4; i++) s[mt][nt][i] = 0.f;
        #pragma unroll
        for (int kk = 0; kk < 128; kk += 8) {
            unsigned a[2][4], bf[4][2];
            #pragma unroll
            for (int mt = 0; mt < 2; mt++) {
                const float* ap = sA + (wm*32 + mt*16 + g) * SA_LD + kk + t4;
                a[mt][0] = __float_as_uint(ap[0]);
                a[mt][1] = __float_as_uint(ap[8 * SA_LD]);
                a[mt][2] = __float_as_uint(ap[4]);
                a[mt][3] = __float_as_uint(ap[8 * SA_LD + 4]);
            }
            #pragma unroll
            for (int nt = 0; nt < 4; nt++) {
                const float* bp = KPb + (wn*32 + nt*8 + g) * SKP_LD + kk + t4;
                bf[nt][0] = __float_as_uint(bp[0]);
                bf[nt][1] = __float_as_uint(bp[4]);
            }
            #pragma unroll
            for (int mt = 0; mt < 2; mt++)
                #pragma unroll
                for (int nt = 0; nt < 4; nt++)
                    mma_tf32(s[mt][nt], a[mt], bf[nt]);
        }
        #pragma unroll
        for (int mt = 0; mt < 2; mt++)
            #pragma unroll
            for (int nt = 0; nt < 4; nt++) {
                float* d = ssc + (wm*32 + mt*16 + g) * SC_LD + wn*32 + nt*8 + t4*2;
                float2 lo; lo.x = s[mt][nt][0] * 0.125f; lo.y = s[mt][nt][1] * 0.125f;
                float2 hi; hi.x = s[mt][nt][2] * 0.125f; hi.y = s[mt][nt][3] * 0.125f;
                *(float2*)d             = lo;
                *(float2*)(d + 8*SC_LD) = hi;
            }
        __syncthreads();

        // online softmax (2 threads per row, 32 scores each)
        {
            float* rp = ssc + srow * SC_LD + ssub * 32;
            float tm = -INFINITY;
            #pragma unroll
            for (int i = 0; i < 32; i++) tm = fmaxf(tm, rp[i]);
            tm = fmaxf(tm, __shfl_xor_sync(0xffffffffu, tm, 1));
            float newm = fmaxf(mi, tm);
            float alpha = __expf(mi - newm);
            float ls = 0.f;
            #pragma unroll
            for (int i = 0; i < 32; i++) {
                float p = __expf(rp[i] - newm);
                ls += p;
                rp[i] = f2tff(p);
            }
            ls += __shfl_xor_sync(0xffffffffu, ls, 1);
            li = li * alpha + ls;
            mi = newm;
            if (ssub == 0) sal[srow] = alpha;
        }
        __syncthreads();

        // AV: O = O*alpha + P.V  (128x64 C, K=64)
        {
            #pragma unroll
            for (int mt = 0; mt < 2; mt++) {
                float aa = sal[wm*32 + mt*16 + g];
                float ab = sal[wm*32 + mt*16 + g + 8];
                #pragma unroll
                for (int nt = 0; nt < 4; nt++) {
                    o[mt][nt][0] *= aa; o[mt][nt][1] *= aa;
                    o[mt][nt][2] *= ab; o[mt][nt][3] *= ab;
                }
            }
            #pragma unroll
            for (int kk = 0; kk < 64; kk += 8) {
                unsigned a[2][4], bf[4][2];
                #pragma unroll
                for (int mt = 0; mt < 2; mt++) {
                    const float* ap = ssc + (wm*32 + mt*16 + g) * SC_LD + kk + t4;
                    a[mt][0] = __float_as_uint(ap[0]);
                    a[mt][1] = __float_as_uint(ap[8 * SC_LD]);
                    a[mt][2] = __float_as_uint(ap[4]);
                    a[mt][3] = __float_as_uint(ap[8 * SC_LD + 4]);
                }
                #pragma unroll
                for (int nt = 0; nt < 4; nt++) {
                    const float* bp = Vb + (kk + t4) * SV_LD + wn*32 + nt*8 + g;
                    bf[nt][0] = __float_as_uint(bp[0]);
                    bf[nt][1] = __float_as_uint(bp[4 * SV_LD]);
                }
                #pragma unroll
                for (int mt = 0; mt < 2; mt++)
                    #pragma unroll
                    for (int nt = 0; nt < 4; nt++)
                        mma_tf32(o[mt][nt], a[mt], bf[nt]);
            }
        }
    }

    // finalize (round for the out-projection's tf32 A operand)
    if (ssub == 0) sli[srow] = li;
    __syncthreads();
    #pragma unroll
    for (int mt = 0; mt < 2; mt++) {
        int r0 = wm*32 + mt*16 + g;
        float inva = 1.f / sli[r0];
        float invb = 1.f / sli[r0 + 8];
        #pragma unroll
        for (int nt = 0; nt < 4; nt++) {
            int dh0 = wn*32 + nt*8 + t4*2;
            float* o1 = g_att + ((size_t)(b * LL + q0 + r0))     * INNER + h * DH + dh0;
            float* o2 = g_att + ((size_t)(b * LL + q0 + r0 + 8)) * INNER + h * DH + dh0;
            o1[0] = f2tff(o[mt][nt][0] * inva); o1[1] = f2tff(o[mt][nt][1] * inva);
            o2[0] = f2tff(o[mt][nt][2] * invb); o2[1] = f2tff(o[mt][nt][3] * invb);
        }
    }
}

// ---------------- launch ----------------
extern "C" void kernel_launch(void* const* d_in, const int* in_sizes, int n_in,
                              void* d_out, int out_size) {
    const float* x      = (const float*)d_in[0];
    const float* gamma  = (const float*)d_in[1];
    const float* beta   = (const float*)d_in[2];
    const float* w_qkv  = (const float*)d_in[3];
    const float* b_qkv  = (const float*)d_in[4];
    const float* w_pos  = (const float*)d_in[5];
    const float* w_out  = (const float*)d_in[6];
    const float* b_out  = (const float*)d_in[7];
    const float* u_bias = (const float*)d_in[8];
    const float* v_bias = (const float*)d_in[9];
    float* out = (float*)d_out;

    float *p_xn, *p_pe;
    cudaGetSymbolAddress((void**)&p_xn, g_xn);
    cudaGetSymbolAddress((void**)&p_pe, g_pe);

    // 1. round weights to tf32 + freq table (independent, tiny)
    {
        int n4 = (3*INNER*DD + INNER*DD + DD*INNER) / 4;
        round_w<<<(n4 + 255) / 256, 256>>>(w_qkv, w_pos, w_out);
        freq_kernel<<<2, 256>>>();
    }

    // 2. fused LayerNorm + PE table
    ln_pe_kernel<<<ROWS + (LL*DD)/256, 256>>>(x, gamma, beta, p_xn, p_pe);

    // 3. fused QKV GEMM + pos GEMM
    {
        dim3 grid((3 * INNER) / 128, ROWS / 128, 2);
        gemm_fused<<<grid, 256>>>(b_qkv);
    }

    // 4. attention
    {
        int smem = AT_SMEM_FLOATS * (int)sizeof(float);   // ~208 KB
        cudaFuncSetAttribute(attn_tc, cudaFuncAttributeMaxDynamicSharedMemorySize, smem);
        dim3 grid(LL / 128, BB * HH);
        attn_tc<<<grid, 256, smem>>>(u_bias, v_bias);
    }

    // 5. out projection -> d_out
    {
        dim3 grid(DD / 128, ROWS / 128);
        gemm_out<<<grid, 256>>>(b_out, out);
    }
}